// round 4
// baseline (speedup 1.0000x reference)
#include <cuda_runtime.h>
#include <cuda_bf16.h>

#define NPTS 4096
#define BATCH 8
#define KNBR 30
#define NEG_SLOPE 0.2f
#define FULL 0xFFFFFFFFu

typedef unsigned long long u64;

// scratch: neighbor indices [B, N, 30]
__device__ int g_idx[BATCH * NPTS * KNBR];

__device__ __forceinline__ unsigned int fkey(float f) {
    unsigned int u = __float_as_uint(f);
    unsigned int mask = (unsigned int)(((int)u) >> 31) | 0x80000000u;
    return u ^ mask;
}

__device__ __forceinline__ float lrelu(float v) {
    return v > 0.0f ? v : NEG_SLOPE * v;
}

__device__ __forceinline__ u64 pack2(float lo, float hi) {
    u64 r;
    asm("mov.b64 %0, {%1, %2};" : "=l"(r) : "f"(lo), "f"(hi));
    return r;
}
__device__ __forceinline__ void unpack2(u64 v, float& lo, float& hi) {
    asm("mov.b64 {%0, %1}, %2;" : "=f"(lo), "=f"(hi) : "l"(v));
}
__device__ __forceinline__ u64 fma2(u64 a, u64 b, u64 c) {
    u64 d;
    asm("fma.rn.f32x2 %0, %1, %2, %3;" : "=l"(d) : "l"(a), "l"(b), "l"(c));
    return d;
}
__device__ __forceinline__ u64 mul2(u64 a, u64 b) {
    u64 d;
    asm("mul.rn.f32x2 %0, %1, %2;" : "=l"(d) : "l"(a), "l"(b));
    return d;
}
__device__ __forceinline__ u64 add2(u64 a, u64 b) {
    u64 d;
    asm("add.rn.f32x2 %0, %1, %2;" : "=l"(d) : "l"(a), "l"(b));
    return d;
}
__device__ __forceinline__ u64 lrelu2(u64 v) {
    float lo, hi;
    unpack2(v, lo, hi);
    return pack2(lrelu(lo), lrelu(hi));
}

// ---------------------------------------------------------------------------
// Kernel 1: KNN — warp-per-query, warp-distributed sorted top-32 list with
// PARALLEL merge-rank insertion (no serial shfl_up chain).
// grid (32, 8), block 512. smem: float4[4096] (64KB) + u64 scatter buf.
// ---------------------------------------------------------------------------
__global__ void __launch_bounds__(512) knn_kernel(const float* __restrict__ x) {
    extern __shared__ float4 p4[];
    __shared__ u64 sbuf[16][32];
    const int b = blockIdx.y;
    const int tid = threadIdx.x;
    const int wid = tid >> 5;
    const int lane = tid & 31;
    const float* xb = x + b * 3 * NPTS;
    u64* sw = sbuf[wid];

    for (int i = tid; i < NPTS; i += 512) {
        float cx = xb[i], cy = xb[NPTS + i], cz = xb[2 * NPTS + i];
        p4[i] = make_float4(cx, cy, cz, cx * cx + cy * cy + cz * cz);
    }
    __syncthreads();

    for (int t = 0; t < 8; ++t) {
        const int q = blockIdx.x * 128 + wid * 8 + t;
        const float4 qv = p4[q];
        const float qq = qv.w;

        u64 L = 0ull;    // lane i = (i+1)-th largest key
        u64 thr = 0ull;  // copy of L[29] (30th best)

        for (int base = 0; base < NPTS; base += 32) {
            const int c = base + lane;
            const float4 cv = p4[c];
            float d = qv.x * cv.x;
            d = fmaf(qv.y, cv.y, d);
            d = fmaf(qv.z, cv.z, d);
            const float pd = fmaf(2.0f, d, -qq) - cv.w;
            const u64 key = ((u64)fkey(pd) << 32) | (unsigned int)(~c);

            unsigned m = __ballot_sync(FULL, key > thr);
            if (m) {
                const bool want = (key > thr);
                int cnt = 0, rank = 0;
                unsigned mm = m;
                while (mm) {
                    const int s = __ffs(mm) - 1;
                    mm &= mm - 1;
                    const u64 ks = __shfl_sync(FULL, key, s);
                    const unsigned b1 = __ballot_sync(FULL, L > ks);
                    const unsigned b2 = __ballot_sync(FULL, want && (key > ks));
                    if (lane == s) rank = __popc(b1) + __popc(b2);
                    cnt += (ks > L) ? 1 : 0;
                }
                const int dest = lane + cnt;
                __syncwarp();
                if (dest < 32) sw[dest] = L;
                if (want && rank < 32) sw[rank] = key;
                __syncwarp();
                L = sw[lane];
                thr = __shfl_sync(FULL, L, 29);
            }
        }

        if (lane < KNBR)
            g_idx[(b * NPTS + q) * KNBR + lane] = (int)(~(unsigned int)L);
        __syncwarp();
    }
}

// ---------------------------------------------------------------------------
// Kernel 2: fused edge-MLP + prefix-softmax pooling, lane-per-neighbor,
// TWO points (A/B) per iteration sharing every w2 smem load.
// Layer-1 row packed (6 w1 pairs + scale + bias) into one 64B smem row.
// ---------------------------------------------------------------------------
#define H2STRIDE 66

__global__ void __launch_bounds__(256, 1) mlp_kernel(
    const float* __restrict__ x,
    const float* __restrict__ w1, const float* __restrict__ g1, const float* __restrict__ b1,
    const float* __restrict__ w2, const float* __restrict__ g2, const float* __restrict__ b2,
    const float* __restrict__ wa, const float* __restrict__ ba,
    const float* __restrict__ ga, const float* __restrict__ bga,
    float* __restrict__ out)
{
    extern __shared__ __align__(16) unsigned char smraw[];
    u64*   w2p   = (u64*)smraw;                 // [64][32]   16384 B
    u64*   w1row = (u64*)(smraw + 16384);       // [32][8]     2048 B
    float* s2v   = (float*)(smraw + 18432);     // [64]
    float* b2v   = (float*)(smraw + 18688);     // [64]
    float* wav   = (float*)(smraw + 18944);     // [64]
    float* wbuf  = (float*)(smraw + 19200);     // [8][2][32]  2048 B
    float* h2b   = (float*)(smraw + 21248);     // [8][2][32][66] 135168 B

    const int tid = threadIdx.x;
    const int wid = tid >> 5;
    const int lane = tid & 31;
    const float rs = rsqrtf(1.0f + 1e-5f);

    for (int idx = tid; idx < 2048; idx += 256) {
        const int c = idx >> 5, ip = idx & 31;
        w2p[c * 32 + ip] = pack2(w2[c * 64 + 2 * ip], w2[c * 64 + 2 * ip + 1]);
    }
    if (tid < 192) {
        const int i = tid % 6, cp = tid / 6;
        w1row[cp * 8 + i] = pack2(w1[(2 * cp) * 6 + i], w1[(2 * cp + 1) * 6 + i]);
    }
    if (tid < 32) {
        w1row[tid * 8 + 6] = pack2(g1[2 * tid] * rs, g1[2 * tid + 1] * rs);
        w1row[tid * 8 + 7] = pack2(b1[2 * tid], b1[2 * tid + 1]);
    }
    if (tid >= 64 && tid < 128) {
        const int c = tid - 64;
        s2v[c] = g2[c] * rs;
        b2v[c] = b2[c];
        wav[c] = wa[c];
    }
    __syncthreads();

    const float ba0 = ba[0];
    const float sa = ga[0] * rs;
    const float bza = bga[0];
    float* h2A = h2b + wid * (2 * 32 * H2STRIDE);
    float* h2B = h2A + 32 * H2STRIDE;
    float* wrowA = wbuf + wid * 64;
    float* wrowB = wrowA + 32;

    for (int tt = 0; tt < 4; ++tt) {
        const int pA = blockIdx.x * 64 + wid * 8 + tt;
        const int pB = pA + 4;
        const int bb = pA >> 12;                 // same batch for A and B
        const int nA = pA & (NPTS - 1), nB = pB & (NPTS - 1);
        const float* xb = x + bb * 3 * NPTS;
        const float cxA = xb[nA], cyA = xb[NPTS + nA], czA = xb[2 * NPTS + nA];
        const float cxB = xb[nB], cyB = xb[NPTS + nB], czB = xb[2 * NPTS + nB];
        const int nbA = (lane < KNBR) ? g_idx[(bb * NPTS + nA) * KNBR + lane] : nA;
        const int nbB = (lane < KNBR) ? g_idx[(bb * NPTS + nB) * KNBR + lane] : nB;

        u64 fA[6], fB[6];
        fA[0] = pack2(xb[nbA] - cxA, xb[nbA] - cxA);
        fA[1] = pack2(xb[NPTS + nbA] - cyA, xb[NPTS + nbA] - cyA);
        fA[2] = pack2(xb[2 * NPTS + nbA] - czA, xb[2 * NPTS + nbA] - czA);
        fA[3] = pack2(cxA, cxA); fA[4] = pack2(cyA, cyA); fA[5] = pack2(czA, czA);
        fB[0] = pack2(xb[nbB] - cxB, xb[nbB] - cxB);
        fB[1] = pack2(xb[NPTS + nbB] - cyB, xb[NPTS + nbB] - cyB);
        fB[2] = pack2(xb[2 * NPTS + nbB] - czB, xb[2 * NPTS + nbB] - czB);
        fB[3] = pack2(cxB, cxB); fB[4] = pack2(cyB, cyB); fB[5] = pack2(czB, czB);

        // ---- layer 1: 32 channel-pairs, shared packed weight rows ----
        u64 h1A[32], h1B[32];
#pragma unroll
        for (int cp = 0; cp < 32; ++cp) {
            const ulonglong4* r4 = (const ulonglong4*)(w1row + cp * 8);
            const ulonglong4 r0 = r4[0];
            const ulonglong4 r1 = r4[1];
            u64 a = mul2(r0.x, fA[0]);
            a = fma2(r0.y, fA[1], a); a = fma2(r0.z, fA[2], a);
            a = fma2(r0.w, fA[3], a); a = fma2(r1.x, fA[4], a);
            a = fma2(r1.y, fA[5], a);
            h1A[cp] = lrelu2(fma2(a, r1.z, r1.w));
            u64 bacc = mul2(r0.x, fB[0]);
            bacc = fma2(r0.y, fB[1], bacc); bacc = fma2(r0.z, fB[2], bacc);
            bacc = fma2(r0.w, fB[3], bacc); bacc = fma2(r1.x, fB[4], bacc);
            bacc = fma2(r1.y, fB[5], bacc);
            h1B[cp] = lrelu2(fma2(bacc, r1.z, r1.w));
        }

        // ---- layer 2: 64-channel matvec, w2 loads shared between A and B ----
        float ajA = 0.0f, ajB = 0.0f;
#pragma unroll 2
        for (int c = 0; c < 64; ++c) {
            const ulonglong2* wr = (const ulonglong2*)(w2p + c * 32);
            u64 aA0 = 0ull, aA1 = 0ull, aB0 = 0ull, aB1 = 0ull;
#pragma unroll
            for (int q8 = 0; q8 < 16; ++q8) {
                const ulonglong2 wv = wr[q8];
                aA0 = fma2(wv.x, h1A[2 * q8], aA0);
                aA1 = fma2(wv.y, h1A[2 * q8 + 1], aA1);
                aB0 = fma2(wv.x, h1B[2 * q8], aB0);
                aB1 = fma2(wv.y, h1B[2 * q8 + 1], aB1);
            }
            float loA, hiA, loB, hiB;
            unpack2(add2(aA0, aA1), loA, hiA);
            unpack2(add2(aB0, aB1), loB, hiB);
            const float hA = lrelu(fmaf(loA + hiA, s2v[c], b2v[c]));
            const float hB = lrelu(fmaf(loB + hiB, s2v[c], b2v[c]));
            h2A[lane * H2STRIDE + c] = hA;
            h2B[lane * H2STRIDE + c] = hB;
            ajA = fmaf(wav[c], hA, ajA);
            ajB = fmaf(wav[c], hB, ajB);
        }

        // ---- attention + prefix softmax weights ----
        ajA = lrelu(fmaf(ajA + ba0, sa, bza));
        ajB = lrelu(fmaf(ajB + ba0, sa, bza));
        if (lane >= KNBR) { ajA = -1e30f; ajB = -1e30f; }
        float mxA = ajA, mxB = ajB;
#pragma unroll
        for (int off = 16; off; off >>= 1) {
            mxA = fmaxf(mxA, __shfl_xor_sync(FULL, mxA, off));
            mxB = fmaxf(mxB, __shfl_xor_sync(FULL, mxB, off));
        }
        const float eA = __expf(ajA - mxA);
        const float eB = __expf(ajB - mxB);
        float scnA = eA, scnB = eB;
#pragma unroll
        for (int off = 1; off < 32; off <<= 1) {
            const float vA = __shfl_up_sync(FULL, scnA, off);
            const float vB = __shfl_up_sync(FULL, scnB, off);
            if (lane >= off) { scnA += vA; scnB += vB; }
        }
        float wsA = 0.0f, wsB = 0.0f;
        {
            const float dA10 = __shfl_sync(FULL, scnA, 9);
            const float dA20 = __shfl_sync(FULL, scnA, 19);
            const float dA30 = __shfl_sync(FULL, scnA, 29);
            const float dB10 = __shfl_sync(FULL, scnB, 9);
            const float dB20 = __shfl_sync(FULL, scnB, 19);
            const float dB30 = __shfl_sync(FULL, scnB, 29);
            if (lane < 10) { wsA += 1.0f / dA10; wsB += 1.0f / dB10; }
            if (lane < 20) { wsA += 1.0f / dA20; wsB += 1.0f / dB20; }
            if (lane < 30) { wsA += 1.0f / dA30; wsB += 1.0f / dB30; }
        }
        wrowA[lane] = eA * wsA * (1.0f / 3.0f);
        wrowB[lane] = eB * wsB * (1.0f / 3.0f);
        __syncwarp();

        // ---- weighted pooled output: lane owns channels (2*lane, 2*lane+1) ----
        u64 accA = 0ull, accB = 0ull;
#pragma unroll
        for (int j = 0; j < KNBR; ++j) {
            const float WjA = wrowA[j];
            const float WjB = wrowB[j];
            const u64 hA = *(const u64*)&h2A[j * H2STRIDE + 2 * lane];
            const u64 hB = *(const u64*)&h2B[j * H2STRIDE + 2 * lane];
            accA = fma2(pack2(WjA, WjA), hA, accA);
            accB = fma2(pack2(WjB, WjB), hB, accB);
        }
        float vA0, vA1, vB0, vB1;
        unpack2(accA, vA0, vA1);
        unpack2(accB, vB0, vB1);
        out[(bb * 64 + 2 * lane) * NPTS + nA] = vA0;
        out[(bb * 64 + 2 * lane + 1) * NPTS + nA] = vA1;
        out[(bb * 64 + 2 * lane) * NPTS + nB] = vB0;
        out[(bb * 64 + 2 * lane + 1) * NPTS + nB] = vB1;
        __syncwarp();
    }
}

extern "C" void kernel_launch(void* const* d_in, const int* in_sizes, int n_in,
                              void* d_out, int out_size) {
    const float* x   = (const float*)d_in[0];
    const float* w1  = (const float*)d_in[1];
    const float* g1  = (const float*)d_in[2];
    const float* b1  = (const float*)d_in[3];
    const float* w2  = (const float*)d_in[4];
    const float* g2  = (const float*)d_in[5];
    const float* b2  = (const float*)d_in[6];
    const float* wa  = (const float*)d_in[7];
    const float* ba  = (const float*)d_in[8];
    const float* ga  = (const float*)d_in[9];
    const float* bga = (const float*)d_in[10];
    float* out = (float*)d_out;

    const int knn_smem = NPTS * 16;  // 64KB dynamic
    cudaFuncSetAttribute(knn_kernel, cudaFuncAttributeMaxDynamicSharedMemorySize, knn_smem);
    const int mlp_smem = 21248 + 8 * 2 * 32 * H2STRIDE * 4;  // 156416 B
    cudaFuncSetAttribute(mlp_kernel, cudaFuncAttributeMaxDynamicSharedMemorySize, mlp_smem);

    knn_kernel<<<dim3(NPTS / 128, BATCH), 512, knn_smem>>>(x);
    mlp_kernel<<<(BATCH * NPTS) / 64, 256, mlp_smem>>>(x, w1, g1, b1, w2, g2, b2,
                                                       wa, ba, ga, bga, out);
}

// round 5
// speedup vs baseline: 1.2852x; 1.2852x over previous
#include <cuda_runtime.h>
#include <cuda_bf16.h>

#define NPTS 4096
#define BATCH 8
#define KNBR 30
#define NEG_SLOPE 0.2f
#define FULL 0xFFFFFFFFu

typedef unsigned long long u64;

// scratch: neighbor indices [B, N, 30]
__device__ int g_idx[BATCH * NPTS * KNBR];

__device__ __forceinline__ unsigned int fkey(float f) {
    unsigned int u = __float_as_uint(f);
    unsigned int mask = (unsigned int)(((int)u) >> 31) | 0x80000000u;
    return u ^ mask;
}

__device__ __forceinline__ float lrelu(float v) {
    return v > 0.0f ? v : NEG_SLOPE * v;
}

__device__ __forceinline__ u64 pack2(float lo, float hi) {
    u64 r;
    asm("mov.b64 %0, {%1, %2};" : "=l"(r) : "f"(lo), "f"(hi));
    return r;
}
__device__ __forceinline__ void unpack2(u64 v, float& lo, float& hi) {
    asm("mov.b64 {%0, %1}, %2;" : "=f"(lo), "=f"(hi) : "l"(v));
}
__device__ __forceinline__ u64 fma2(u64 a, u64 b, u64 c) {
    u64 d;
    asm("fma.rn.f32x2 %0, %1, %2, %3;" : "=l"(d) : "l"(a), "l"(b), "l"(c));
    return d;
}
__device__ __forceinline__ u64 mul2(u64 a, u64 b) {
    u64 d;
    asm("mul.rn.f32x2 %0, %1, %2;" : "=l"(d) : "l"(a), "l"(b));
    return d;
}
__device__ __forceinline__ u64 add2(u64 a, u64 b) {
    u64 d;
    asm("add.rn.f32x2 %0, %1, %2;" : "=l"(d) : "l"(a), "l"(b));
    return d;
}
__device__ __forceinline__ u64 lrelu2(u64 v) {
    float lo, hi;
    unpack2(v, lo, hi);
    return pack2(lrelu(lo), lrelu(hi));
}

// ---------------------------------------------------------------------------
// Kernel 1: KNN — warp-per-2-queries, warp-distributed sorted top-32 lists,
// serial shfl-up insertion (R3 style), thresholds kept in registers.
// Two independent insert chains per warp interleave to hide shfl latency.
// grid (32, 8), block 512 (16 warps). smem: float4[4096] = 64KB.
// ---------------------------------------------------------------------------
__global__ void __launch_bounds__(512) knn_kernel(const float* __restrict__ x) {
    extern __shared__ float4 p4[];
    const int b = blockIdx.y;
    const int tid = threadIdx.x;
    const int wid = tid >> 5;
    const int lane = tid & 31;
    const float* xb = x + b * 3 * NPTS;

    for (int i = tid; i < NPTS; i += 512) {
        float cx = xb[i], cy = xb[NPTS + i], cz = xb[2 * NPTS + i];
        p4[i] = make_float4(cx, cy, cz, cx * cx + cy * cy + cz * cz);
    }
    __syncthreads();

    for (int t = 0; t < 4; ++t) {
        const int qA = blockIdx.x * 128 + wid * 8 + t;
        const int qB = qA + 4;
        const float4 qvA = p4[qA];
        const float4 qvB = p4[qB];
        const float qqA = qvA.w, qqB = qvB.w;

        u64 LA = 0ull, LB = 0ull;
        u64 thrA = 0ull, thrB = 0ull;

        for (int base = 0; base < NPTS; base += 32) {
            const int c = base + lane;
            const float4 cv = p4[c];
            float dA = qvA.x * cv.x;
            dA = fmaf(qvA.y, cv.y, dA);
            dA = fmaf(qvA.z, cv.z, dA);
            float dB = qvB.x * cv.x;
            dB = fmaf(qvB.y, cv.y, dB);
            dB = fmaf(qvB.z, cv.z, dB);
            const float pdA = fmaf(2.0f, dA, -qqA) - cv.w;
            const float pdB = fmaf(2.0f, dB, -qqB) - cv.w;
            const u64 keyA = ((u64)fkey(pdA) << 32) | (unsigned int)(~c);
            const u64 keyB = ((u64)fkey(pdB) << 32) | (unsigned int)(~c);

            unsigned mA = __ballot_sync(FULL, keyA > thrA);
            unsigned mB = __ballot_sync(FULL, keyB > thrB);
            if (mA | mB) {
                while (mA) {
                    const int src = __ffs(mA) - 1;
                    mA &= mA - 1;
                    const u64 k = __shfl_sync(FULL, keyA, src);
                    u64 prev = __shfl_up_sync(FULL, LA, 1);
                    if (lane == 0) prev = ~0ull;
                    LA = (LA > k) ? LA : ((prev > k) ? k : prev);
                }
                while (mB) {
                    const int src = __ffs(mB) - 1;
                    mB &= mB - 1;
                    const u64 k = __shfl_sync(FULL, keyB, src);
                    u64 prev = __shfl_up_sync(FULL, LB, 1);
                    if (lane == 0) prev = ~0ull;
                    LB = (LB > k) ? LB : ((prev > k) ? k : prev);
                }
                thrA = __shfl_sync(FULL, LA, 29);
                thrB = __shfl_sync(FULL, LB, 29);
            }
        }

        if (lane < KNBR) {
            g_idx[(b * NPTS + qA) * KNBR + lane] = (int)(~(unsigned int)LA);
            g_idx[(b * NPTS + qB) * KNBR + lane] = (int)(~(unsigned int)LB);
        }
        __syncwarp();
    }
}

// ---------------------------------------------------------------------------
// Kernel 2: fused edge-MLP + prefix-softmax pooling, lane-per-neighbor,
// TWO points (A/B) per iteration sharing w2 loads; layer-2 processes TWO
// channels per inner block (8 independent fma2 chains) for latency hiding.
// ---------------------------------------------------------------------------
#define H2STRIDE 66

__global__ void __launch_bounds__(256, 1) mlp_kernel(
    const float* __restrict__ x,
    const float* __restrict__ w1, const float* __restrict__ g1, const float* __restrict__ b1,
    const float* __restrict__ w2, const float* __restrict__ g2, const float* __restrict__ b2,
    const float* __restrict__ wa, const float* __restrict__ ba,
    const float* __restrict__ ga, const float* __restrict__ bga,
    float* __restrict__ out)
{
    extern __shared__ __align__(16) unsigned char smraw[];
    u64*   w2p   = (u64*)smraw;                 // [64][32]   16384 B
    u64*   w1row = (u64*)(smraw + 16384);       // [32][8]     2048 B
    float* s2v   = (float*)(smraw + 18432);     // [64]
    float* b2v   = (float*)(smraw + 18688);     // [64]
    float* wav   = (float*)(smraw + 18944);     // [64]
    float* wbuf  = (float*)(smraw + 19200);     // [8][2][32]  2048 B
    float* h2b   = (float*)(smraw + 21248);     // [8][2][32][66] 135168 B

    const int tid = threadIdx.x;
    const int wid = tid >> 5;
    const int lane = tid & 31;
    const float rs = rsqrtf(1.0f + 1e-5f);

    for (int idx = tid; idx < 2048; idx += 256) {
        const int c = idx >> 5, ip = idx & 31;
        w2p[c * 32 + ip] = pack2(w2[c * 64 + 2 * ip], w2[c * 64 + 2 * ip + 1]);
    }
    if (tid < 192) {
        const int i = tid % 6, cp = tid / 6;
        w1row[cp * 8 + i] = pack2(w1[(2 * cp) * 6 + i], w1[(2 * cp + 1) * 6 + i]);
    }
    if (tid < 32) {
        w1row[tid * 8 + 6] = pack2(g1[2 * tid] * rs, g1[2 * tid + 1] * rs);
        w1row[tid * 8 + 7] = pack2(b1[2 * tid], b1[2 * tid + 1]);
    }
    if (tid >= 64 && tid < 128) {
        const int c = tid - 64;
        s2v[c] = g2[c] * rs;
        b2v[c] = b2[c];
        wav[c] = wa[c];
    }
    __syncthreads();

    const float ba0 = ba[0];
    const float sa = ga[0] * rs;
    const float bza = bga[0];
    float* h2A = h2b + wid * (2 * 32 * H2STRIDE);
    float* h2B = h2A + 32 * H2STRIDE;
    float* wrowA = wbuf + wid * 64;
    float* wrowB = wrowA + 32;

    for (int tt = 0; tt < 4; ++tt) {
        const int pA = blockIdx.x * 64 + wid * 8 + tt;
        const int pB = pA + 4;
        const int bb = pA >> 12;
        const int nA = pA & (NPTS - 1), nB = pB & (NPTS - 1);
        const float* xb = x + bb * 3 * NPTS;
        const float cxA = xb[nA], cyA = xb[NPTS + nA], czA = xb[2 * NPTS + nA];
        const float cxB = xb[nB], cyB = xb[NPTS + nB], czB = xb[2 * NPTS + nB];
        const int nbA = (lane < KNBR) ? g_idx[(bb * NPTS + nA) * KNBR + lane] : nA;
        const int nbB = (lane < KNBR) ? g_idx[(bb * NPTS + nB) * KNBR + lane] : nB;

        u64 fA[6], fB[6];
        {
            const float ax = xb[nbA] - cxA, ay = xb[NPTS + nbA] - cyA, az = xb[2 * NPTS + nbA] - czA;
            const float bx = xb[nbB] - cxB, by = xb[NPTS + nbB] - cyB, bz = xb[2 * NPTS + nbB] - czB;
            fA[0] = pack2(ax, ax); fA[1] = pack2(ay, ay); fA[2] = pack2(az, az);
            fA[3] = pack2(cxA, cxA); fA[4] = pack2(cyA, cyA); fA[5] = pack2(czA, czA);
            fB[0] = pack2(bx, bx); fB[1] = pack2(by, by); fB[2] = pack2(bz, bz);
            fB[3] = pack2(cxB, cxB); fB[4] = pack2(cyB, cyB); fB[5] = pack2(czB, czB);
        }

        // ---- layer 1: 32 channel-pairs, shared packed weight rows ----
        u64 h1A[32], h1B[32];
#pragma unroll
        for (int cp = 0; cp < 32; ++cp) {
            const ulonglong4* r4 = (const ulonglong4*)(w1row + cp * 8);
            const ulonglong4 r0 = r4[0];
            const ulonglong4 r1 = r4[1];
            u64 a = mul2(r0.x, fA[0]);
            a = fma2(r0.y, fA[1], a); a = fma2(r0.z, fA[2], a);
            a = fma2(r0.w, fA[3], a); a = fma2(r1.x, fA[4], a);
            a = fma2(r1.y, fA[5], a);
            h1A[cp] = lrelu2(fma2(a, r1.z, r1.w));
            u64 bacc = mul2(r0.x, fB[0]);
            bacc = fma2(r0.y, fB[1], bacc); bacc = fma2(r0.z, fB[2], bacc);
            bacc = fma2(r0.w, fB[3], bacc); bacc = fma2(r1.x, fB[4], bacc);
            bacc = fma2(r1.y, fB[5], bacc);
            h1B[cp] = lrelu2(fma2(bacc, r1.z, r1.w));
        }

        // ---- layer 2: two channels per block, 8 independent fma2 chains ----
        float ajA = 0.0f, ajB = 0.0f;
#pragma unroll 1
        for (int c = 0; c < 64; c += 2) {
            const ulonglong2* wr0 = (const ulonglong2*)(w2p + c * 32);
            const ulonglong2* wr1 = (const ulonglong2*)(w2p + (c + 1) * 32);
            u64 aA0 = 0ull, aA1 = 0ull, bA0 = 0ull, bA1 = 0ull;
            u64 aB0 = 0ull, aB1 = 0ull, bB0 = 0ull, bB1 = 0ull;
#pragma unroll
            for (int q8 = 0; q8 < 16; ++q8) {
                const ulonglong2 wv0 = wr0[q8];
                const ulonglong2 wv1 = wr1[q8];
                const u64 hA0 = h1A[2 * q8], hA1 = h1A[2 * q8 + 1];
                const u64 hB0 = h1B[2 * q8], hB1 = h1B[2 * q8 + 1];
                aA0 = fma2(wv0.x, hA0, aA0);
                aA1 = fma2(wv0.y, hA1, aA1);
                bA0 = fma2(wv1.x, hA0, bA0);
                bA1 = fma2(wv1.y, hA1, bA1);
                aB0 = fma2(wv0.x, hB0, aB0);
                aB1 = fma2(wv0.y, hB1, aB1);
                bB0 = fma2(wv1.x, hB0, bB0);
                bB1 = fma2(wv1.y, hB1, bB1);
            }
            float l0, h0, l1, h1v, l2, h2v, l3, h3;
            unpack2(add2(aA0, aA1), l0, h0);
            unpack2(add2(bA0, bA1), l1, h1v);
            unpack2(add2(aB0, aB1), l2, h2v);
            unpack2(add2(bB0, bB1), l3, h3);
            const float hAc0 = lrelu(fmaf(l0 + h0, s2v[c], b2v[c]));
            const float hAc1 = lrelu(fmaf(l1 + h1v, s2v[c + 1], b2v[c + 1]));
            const float hBc0 = lrelu(fmaf(l2 + h2v, s2v[c], b2v[c]));
            const float hBc1 = lrelu(fmaf(l3 + h3, s2v[c + 1], b2v[c + 1]));
            *(u64*)&h2A[lane * H2STRIDE + c] = pack2(hAc0, hAc1);
            *(u64*)&h2B[lane * H2STRIDE + c] = pack2(hBc0, hBc1);
            ajA = fmaf(wav[c], hAc0, ajA);
            ajA = fmaf(wav[c + 1], hAc1, ajA);
            ajB = fmaf(wav[c], hBc0, ajB);
            ajB = fmaf(wav[c + 1], hBc1, ajB);
        }

        // ---- attention + prefix softmax weights ----
        ajA = lrelu(fmaf(ajA + ba0, sa, bza));
        ajB = lrelu(fmaf(ajB + ba0, sa, bza));
        if (lane >= KNBR) { ajA = -1e30f; ajB = -1e30f; }
        float mxA = ajA, mxB = ajB;
#pragma unroll
        for (int off = 16; off; off >>= 1) {
            mxA = fmaxf(mxA, __shfl_xor_sync(FULL, mxA, off));
            mxB = fmaxf(mxB, __shfl_xor_sync(FULL, mxB, off));
        }
        const float eA = __expf(ajA - mxA);
        const float eB = __expf(ajB - mxB);
        float scnA = eA, scnB = eB;
#pragma unroll
        for (int off = 1; off < 32; off <<= 1) {
            const float vA = __shfl_up_sync(FULL, scnA, off);
            const float vB = __shfl_up_sync(FULL, scnB, off);
            if (lane >= off) { scnA += vA; scnB += vB; }
        }
        float wsA = 0.0f, wsB = 0.0f;
        {
            const float dA10 = __shfl_sync(FULL, scnA, 9);
            const float dA20 = __shfl_sync(FULL, scnA, 19);
            const float dA30 = __shfl_sync(FULL, scnA, 29);
            const float dB10 = __shfl_sync(FULL, scnB, 9);
            const float dB20 = __shfl_sync(FULL, scnB, 19);
            const float dB30 = __shfl_sync(FULL, scnB, 29);
            if (lane < 10) { wsA += 1.0f / dA10; wsB += 1.0f / dB10; }
            if (lane < 20) { wsA += 1.0f / dA20; wsB += 1.0f / dB20; }
            if (lane < 30) { wsA += 1.0f / dA30; wsB += 1.0f / dB30; }
        }
        wrowA[lane] = eA * wsA * (1.0f / 3.0f);
        wrowB[lane] = eB * wsB * (1.0f / 3.0f);
        __syncwarp();

        // ---- weighted pooled output: lane owns channels (2*lane, 2*lane+1) ----
        u64 accA = 0ull, accB = 0ull;
#pragma unroll
        for (int j = 0; j < KNBR; ++j) {
            const float WjA = wrowA[j];
            const float WjB = wrowB[j];
            const u64 hA = *(const u64*)&h2A[j * H2STRIDE + 2 * lane];
            const u64 hB = *(const u64*)&h2B[j * H2STRIDE + 2 * lane];
            accA = fma2(pack2(WjA, WjA), hA, accA);
            accB = fma2(pack2(WjB, WjB), hB, accB);
        }
        float vA0, vA1, vB0, vB1;
        unpack2(accA, vA0, vA1);
        unpack2(accB, vB0, vB1);
        out[(bb * 64 + 2 * lane) * NPTS + nA] = vA0;
        out[(bb * 64 + 2 * lane + 1) * NPTS + nA] = vA1;
        out[(bb * 64 + 2 * lane) * NPTS + nB] = vB0;
        out[(bb * 64 + 2 * lane + 1) * NPTS + nB] = vB1;
        __syncwarp();
    }
}

extern "C" void kernel_launch(void* const* d_in, const int* in_sizes, int n_in,
                              void* d_out, int out_size) {
    const float* x   = (const float*)d_in[0];
    const float* w1  = (const float*)d_in[1];
    const float* g1  = (const float*)d_in[2];
    const float* b1  = (const float*)d_in[3];
    const float* w2  = (const float*)d_in[4];
    const float* g2  = (const float*)d_in[5];
    const float* b2  = (const float*)d_in[6];
    const float* wa  = (const float*)d_in[7];
    const float* ba  = (const float*)d_in[8];
    const float* ga  = (const float*)d_in[9];
    const float* bga = (const float*)d_in[10];
    float* out = (float*)d_out;

    const int knn_smem = NPTS * 16;  // 64KB dynamic
    cudaFuncSetAttribute(knn_kernel, cudaFuncAttributeMaxDynamicSharedMemorySize, knn_smem);
    const int mlp_smem = 21248 + 8 * 2 * 32 * H2STRIDE * 4;  // 156416 B
    cudaFuncSetAttribute(mlp_kernel, cudaFuncAttributeMaxDynamicSharedMemorySize, mlp_smem);

    knn_kernel<<<dim3(NPTS / 128, BATCH), 512, knn_smem>>>(x);
    mlp_kernel<<<(BATCH * NPTS) / 64, 256, mlp_smem>>>(x, w1, g1, b1, w2, g2, b2,
                                                       wa, ba, ga, bga, out);
}